// round 12
// baseline (speedup 1.0000x reference)
#include <cuda_runtime.h>
#include <math.h>

// Problem constants (fixed by the reference)
#define BB   16384
#define KK   50
#define HH   64
#define REGC 0.01f
#define GRID 1024
#define UPB  16        // users per block: GRID*UPB == BB

// Bulk-transferred bytes per user stage: 50 rows * 256B + ue 256B
#define STAGE_TX (KK * 256 + 256)

// [0]=sum sq err, [1]=sum ||ie||, [2]=sum ||ue||
// Statically zero-init; last block re-zeroes after use (invariant per replay).
__device__ float    g_scratch[3];
__device__ unsigned g_count;

__device__ __forceinline__ void cpa4(void* s, const void* g) {
    unsigned sa = (unsigned)__cvta_generic_to_shared(s);
    asm volatile("cp.async.ca.shared.global [%0], [%1], 4;\n" :: "r"(sa), "l"(g));
}
__device__ __forceinline__ void pf_l2(const void* g) {
    asm volatile("prefetch.global.L2 [%0];" :: "l"(g));
}
// One 256B row gather on the bulk/TMA engine; completion signaled on mbar.
__device__ __forceinline__ void bulk256(void* s, const void* g, unsigned mbar) {
    unsigned sa = (unsigned)__cvta_generic_to_shared(s);
    asm volatile(
        "cp.async.bulk.shared::cluster.global.mbarrier::complete_tx::bytes "
        "[%0], [%1], %2, [%3];\n"
        :: "r"(sa), "l"(g), "r"(256u), "r"(mbar) : "memory");
}
__device__ __forceinline__ void mbar_init(unsigned mbar, unsigned cnt) {
    asm volatile("mbarrier.init.shared.b64 [%0], %1;" :: "r"(mbar), "r"(cnt) : "memory");
}
__device__ __forceinline__ void mbar_expect(unsigned mbar, unsigned bytes) {
    asm volatile("mbarrier.arrive.expect_tx.shared.b64 _, [%0], %1;"
                 :: "r"(mbar), "r"(bytes) : "memory");
}
__device__ __forceinline__ void mbar_wait(unsigned mbar, unsigned parity) {
    asm volatile(
        "{\n\t.reg .pred P;\n"
        "WAIT_%=:\n\t"
        "mbarrier.try_wait.parity.acquire.cta.shared::cta.b64 P, [%0], %1, 0x989680;\n\t"
        "@P bra.uni DONE_%=;\n\t"
        "bra.uni WAIT_%=;\n"
        "DONE_%=:\n\t}"
        :: "r"(mbar), "r"(parity) : "memory");
}

__global__ __launch_bounds__(128, 8) void mf_pipe_kernel(
    const float* __restrict__ uw,      // [100000,64]
    const float* __restrict__ iw,      // [1000000,64]
    const float* __restrict__ ub,      // [100000,1]
    const float* __restrict__ ib,      // [1000000,1]
    const float* __restrict__ bias,    // [1]
    const float* __restrict__ target,  // [B,K]
    const int*   __restrict__ user,    // [B]
    const int*   __restrict__ item,    // [B,K]
    float* __restrict__ out)           // [B*K + 1]
{
    __shared__ __align__(16) float rows_s[2][KK][HH];   // 25.6 KB, bulk dst
    __shared__ __align__(16) float ue_s[2][HH];
    __shared__ float tgt_s[2][KK];
    __shared__ float ib_s[2][KK];
    __shared__ int   itm_s[2][KK];
    __shared__ int   usr_s[2];
    __shared__ float ub_s[2];
    __shared__ float pred_s[KK];
    __shared__ float ms_s[16], ns_s[16];
    __shared__ __align__(8) unsigned long long mbar_s[2];

    const int tid  = threadIdx.x;
    const int warp = tid >> 5;
    const int lane = tid & 31;
    // Compute-phase layout: 8 lanes per item
    const int slot = tid >> 3;          // 0..15 : item slot within round
    const int sub  = tid & 7;           // 0..7  : lane within item

    const unsigned mb0 = (unsigned)__cvta_generic_to_shared(&mbar_s[0]);
    const unsigned mb1 = (unsigned)__cvta_generic_to_shared(&mbar_s[1]);

    const int   b0    = blockIdx.x * UPB;
    const float gbias = bias[0];

    // ---- Init mbarriers (arrive count 1: the expect_tx arrive) ----
    if (tid == 0) { mbar_init(mb0, 1); mbar_init(mb1, 1); }

    // ---- Prologue: indices for b0 (stage 0) and b0+1 (stage 1) ----
    if (tid < KK) {
        itm_s[0][tid] = item[b0 * KK + tid];
        itm_s[1][tid] = item[(b0 + 1) * KK + tid];
    }
    if (tid == 0) { usr_s[0] = user[b0]; usr_s[1] = user[b0 + 1]; }
    __syncthreads();

    // Issue group for b0 into stage 0
    {
        const int u0 = usr_s[0];
        if (tid == 0) mbar_expect(mb0, STAGE_TX);
        if (tid < KK)  bulk256(&rows_s[0][tid][0], iw + (size_t)itm_s[0][tid] * HH, mb0);
        if (tid == KK) bulk256(&ue_s[0][0],        uw + (size_t)u0 * HH,            mb0);
        if (tid < KK) {
            cpa4(&ib_s[0][tid],  ib + itm_s[0][tid]);
            cpa4(&tgt_s[0][tid], target + (size_t)b0 * KK + tid);
        }
        if (tid == 0) cpa4(&ub_s[0], ub + u0);
        asm volatile("cp.async.commit_group;\n" ::: "memory");
    }

    float macc = 0.0f, nacc = 0.0f, uacc = 0.0f;

    #pragma unroll 1
    for (int i = 0; i < UPB; ++i) {
        const int b   = b0 + i;
        const int cur = i & 1;
        const int nxt = cur ^ 1;
        const unsigned mbc = cur ? mb1 : mb0;
        const unsigned mbn = cur ? mb0 : mb1;

        // Issue group for b+1 into stage nxt (indices already staged; rows
        // were L2-prefetched one iteration ago -> short-latency fill)
        if (i + 1 < UPB) {
            const int un = usr_s[nxt];
            if (tid == 0) mbar_expect(mbn, STAGE_TX);
            if (tid < KK)  bulk256(&rows_s[nxt][tid][0], iw + (size_t)itm_s[nxt][tid] * HH, mbn);
            if (tid == KK) bulk256(&ue_s[nxt][0],        uw + (size_t)un * HH,              mbn);
            if (tid < KK) {
                cpa4(&ib_s[nxt][tid],  ib + itm_s[nxt][tid]);
                cpa4(&tgt_s[nxt][tid], target + (size_t)(b + 1) * KK + tid);
            }
            if (tid == 0) cpa4(&ub_s[nxt], ub + un);
            asm volatile("cp.async.commit_group;\n" ::: "memory");
        }

        // Kick off index loads for b+2 (latency hidden by compute below)
        int my_itm = 0, my_usr = 0;
        if (i + 2 < UPB) {
            if (tid < KK) my_itm = item[(size_t)(b + 2) * KK + tid];
            if (tid == 0) my_usr = user[b + 2];
        }

        // Wait: small cp.async group for b, then bulk mbarrier for b
        if (i + 1 < UPB) asm volatile("cp.async.wait_group 1;\n" ::: "memory");
        else             asm volatile("cp.async.wait_group 0;\n" ::: "memory");
        mbar_wait(mbc, (unsigned)((i >> 1) & 1));
        __syncthreads();

        // Stage indices for b+2 into the freed slot, and L2-prefetch b+2's
        // rows now: DRAM latency pre-paid before next iteration's bulk fill.
        if (i + 2 < UPB) {
            if (tid < KK) {
                itm_s[cur][tid] = my_itm;
                const char* p = (const char*)(iw + (size_t)my_itm * HH);
                pf_l2(p);
                pf_l2(p + 128);
            }
            if (tid == 0) usr_s[cur] = my_usr;
        }

        // ---- Compute user b from stage cur: 8 lanes per item ----
        const float ubv = ub_s[cur];
        float4 ua  = ((const float4*)ue_s[cur])[sub];
        float4 ub4 = ((const float4*)ue_s[cur])[sub + 8];
        ua.x += ubv; ua.y += ubv; ua.z += ubv; ua.w += ubv;
        ub4.x += ubv; ub4.y += ubv; ub4.z += ubv; ub4.w += ubv;

        if (warp == 0) {   // ||ue||: lanes 0-7 hold the full vector
            float usq = ua.x*ua.x + ua.y*ua.y + ua.z*ua.z + ua.w*ua.w
                      + ub4.x*ub4.x + ub4.y*ub4.y + ub4.z*ub4.z + ub4.w*ub4.w;
            #pragma unroll
            for (int m = 4; m >= 1; m >>= 1)
                usq += __shfl_xor_sync(0xffffffffu, usq, m);
            if (lane == 0) uacc += sqrtf(usq);
        }

        #pragma unroll
        for (int r = 0; r < 4; ++r) {
            const int k   = r * 16 + slot;
            const bool on = (k < KK);
            const int kc  = on ? k : (KK - 1);  // clamp: keep loads in-bounds

            const float bv = ib_s[cur][kc];
            const float4 wa = ((const float4*)rows_s[cur][kc])[sub];
            const float4 wb = ((const float4*)rows_s[cur][kc])[sub + 8];

            float4 ea, eb;
            ea.x = wa.x + bv; ea.y = wa.y + bv; ea.z = wa.z + bv; ea.w = wa.w + bv;
            eb.x = wb.x + bv; eb.y = wb.y + bv; eb.z = wb.z + bv; eb.w = wb.w + bv;

            float dot = ea.x*ua.x + ea.y*ua.y + ea.z*ua.z + ea.w*ua.w
                      + eb.x*ub4.x + eb.y*ub4.y + eb.z*ub4.z + eb.w*ub4.w;
            float sq  = ea.x*ea.x + ea.y*ea.y + ea.z*ea.z + ea.w*ea.w
                      + eb.x*eb.x + eb.y*eb.y + eb.z*eb.z + eb.w*eb.w;

            #pragma unroll
            for (int m = 4; m >= 1; m >>= 1) {
                dot += __shfl_xor_sync(0xffffffffu, dot, m);
                sq  += __shfl_xor_sync(0xffffffffu, sq,  m);
            }

            if (on && sub == 0) {
                const float pred = dot + gbias;
                pred_s[k] = pred;
                const float d = pred - tgt_s[cur][k];
                macc += d * d;
                nacc += sqrtf(sq);
            }
        }
        __syncthreads();   // pred_s complete; stage cur free; itm_s[cur] visible

        // Coalesced prediction store
        if (tid < KK) out[(size_t)b * KK + tid] = pred_s[tid];
    }

    // ---- Block reduce (16 leaders: tid%8==0) + global accumulate ----
    if (sub == 0) { ms_s[slot] = macc; ns_s[slot] = nacc; }
    __syncthreads();
    if (tid == 0) {
        float m = 0.0f, n = 0.0f;
        #pragma unroll
        for (int j = 0; j < 16; ++j) { m += ms_s[j]; n += ns_s[j]; }
        atomicAdd(&g_scratch[0], m);
        atomicAdd(&g_scratch[1], n);
        atomicAdd(&g_scratch[2], uacc);
        __threadfence();
        const unsigned t = atomicAdd(&g_count, 1u);
        if (t == (unsigned)(gridDim.x - 1)) {
            const float s0 = atomicAdd(&g_scratch[0], 0.0f);
            const float s1 = atomicAdd(&g_scratch[1], 0.0f);
            const float s2 = atomicAdd(&g_scratch[2], 0.0f);
            const float inv_bk = 1.0f / (float)((size_t)BB * KK);
            out[(size_t)BB * KK] = s0 * inv_bk
                                 + REGC * (s2 * (1.0f / (float)BB))
                                 + REGC * (s1 * inv_bk);
            g_scratch[0] = 0.0f; g_scratch[1] = 0.0f; g_scratch[2] = 0.0f;
            g_count = 0u;
        }
    }
}

extern "C" void kernel_launch(void* const* d_in, const int* in_sizes, int n_in,
                              void* d_out, int out_size) {
    const float* uw     = (const float*)d_in[0];
    const float* iw     = (const float*)d_in[1];
    const float* ub     = (const float*)d_in[2];
    const float* ib     = (const float*)d_in[3];
    const float* bias   = (const float*)d_in[4];
    const float* target = (const float*)d_in[5];
    const int*   user   = (const int*)d_in[6];
    const int*   item   = (const int*)d_in[7];
    float* out = (float*)d_out;

    mf_pipe_kernel<<<GRID, 128>>>(uw, iw, ub, ib, bias, target, user, item, out);
}

// round 14
// speedup vs baseline: 1.6402x; 1.6402x over previous
#include <cuda_runtime.h>
#include <math.h>

// Problem constants (fixed by the reference)
#define BB   16384
#define KK   50
#define HH   64
#define REGC 0.01f
#define GRID 1024
#define UPB  16        // users per block: GRID*UPB == BB

// [0]=sum sq err, [1]=sum ||ie||, [2]=sum ||ue||
// Statically zero-init; last block re-zeroes after use (invariant per replay).
__device__ float    g_scratch[3];
__device__ unsigned g_count;

__device__ __forceinline__ void cpa16(void* s, const void* g) {
    unsigned sa = (unsigned)__cvta_generic_to_shared(s);
    asm volatile("cp.async.cg.shared.global [%0], [%1], 16;\n" :: "r"(sa), "l"(g));
}
__device__ __forceinline__ void cpa4(void* s, const void* g) {
    unsigned sa = (unsigned)__cvta_generic_to_shared(s);
    asm volatile("cp.async.ca.shared.global [%0], [%1], 4;\n" :: "r"(sa), "l"(g));
}
__device__ __forceinline__ void pf_l2(const void* g) {
    asm volatile("prefetch.global.L2 [%0];" :: "l"(g));
}

__global__ __launch_bounds__(128, 8) void mf_pipe_kernel(
    const float* __restrict__ uw,      // [100000,64]
    const float* __restrict__ iw,      // [1000000,64]
    const float* __restrict__ ub,      // [100000,1]
    const float* __restrict__ ib,      // [1000000,1]
    const float* __restrict__ bias,    // [1]
    const float* __restrict__ target,  // [B,K]
    const int*   __restrict__ user,    // [B]
    const int*   __restrict__ item,    // [B,K]
    float* __restrict__ out)           // [B*K + 1]
{
    __shared__ float rows_s[2][KK][HH];   // 25.6 KB
    __shared__ float ue_s[2][HH];
    __shared__ float tgt_s[2][KK];
    __shared__ float ib_s[2][KK];
    __shared__ int   itm_s[3][KK];        // 3-slot index ring (prefetch depth 3)
    __shared__ int   usr_s[3];
    __shared__ float ub_s[2];
    __shared__ float pred_s[KK];
    __shared__ float ms_s[16], ns_s[16];

    const int tid  = threadIdx.x;
    const int warp = tid >> 5;
    const int lane = tid & 31;
    // Load-phase layout: half-warp per row (256B contiguous, conflict-free)
    const int half = (lane >> 4) & 1;
    const int hl   = lane & 15;
    const int hw   = warp * 2 + half;   // half-warp id 0..7
    // Compute-phase layout: 8 lanes per item
    const int slot = tid >> 3;          // 0..15 : item slot within round
    const int sub  = tid & 7;           // 0..7  : lane within item

    const int   b0    = blockIdx.x * UPB;
    const float gbias = bias[0];

    // ---- Prologue: indices for b0..b0+2 into ring slots 0..2 ----
    if (tid < KK) {
        itm_s[0][tid] = item[(size_t)b0 * KK + tid];
        itm_s[1][tid] = item[(size_t)(b0 + 1) * KK + tid];
        itm_s[2][tid] = item[(size_t)(b0 + 2) * KK + tid];
    }
    if (tid == 0) {
        usr_s[0] = user[b0]; usr_s[1] = user[b0 + 1]; usr_s[2] = user[b0 + 2];
    }
    __syncthreads();

    // L2-prefetch b0+2's rows (cp.async'd at i=1, computed at i=2)
    if (tid < KK) {
        const char* p = (const char*)(iw + (size_t)itm_s[2][tid] * HH);
        pf_l2(p);
        pf_l2(p + 128);
    }

    // Issue gather group for b0 into stage 0
    {
        const int u0 = usr_s[0];
        #pragma unroll
        for (int r = 0; r < 7; ++r) {
            const int k = r * 8 + hw;
            if (k < KK)
                cpa16(&rows_s[0][k][hl * 4], iw + (size_t)itm_s[0][k] * HH + hl * 4);
        }
        if (tid < 16) cpa16(&ue_s[0][tid * 4], uw + (size_t)u0 * HH + tid * 4);
        if (tid < KK) {
            cpa4(&ib_s[0][tid],  ib + itm_s[0][tid]);
            cpa4(&tgt_s[0][tid], target + (size_t)b0 * KK + tid);
        }
        if (tid == 0) cpa4(&ub_s[0], ub + u0);
        asm volatile("cp.async.commit_group;\n" ::: "memory");
    }

    float macc = 0.0f, nacc = 0.0f, uacc = 0.0f;

    #pragma unroll 1
    for (int i = 0; i < UPB; ++i) {
        const int b    = b0 + i;
        const int cur  = i & 1;          // smem data stage
        const int nxt  = cur ^ 1;
        const int icur = i % 3;          // index-ring slot for b (dead after wait)
        const int inxt = (i + 1) % 3;    // slot holding b+1's indices

        // Issue gather group for b+1 into stage nxt (rows L2-prefetched two
        // iterations ago -> short-latency fill)
        if (i + 1 < UPB) {
            const int un = usr_s[inxt];
            #pragma unroll
            for (int r = 0; r < 7; ++r) {
                const int k = r * 8 + hw;
                if (k < KK)
                    cpa16(&rows_s[nxt][k][hl * 4], iw + (size_t)itm_s[inxt][k] * HH + hl * 4);
            }
            if (tid < 16) cpa16(&ue_s[nxt][tid * 4], uw + (size_t)un * HH + tid * 4);
            if (tid < KK) {
                cpa4(&ib_s[nxt][tid],  ib + itm_s[inxt][tid]);
                cpa4(&tgt_s[nxt][tid], target + (size_t)(b + 1) * KK + tid);
            }
            if (tid == 0) cpa4(&ub_s[nxt], ub + un);
            asm volatile("cp.async.commit_group;\n" ::: "memory");
        }

        // Kick off index loads for b+3 (latency hidden by compute below)
        int my_itm = 0, my_usr = 0;
        if (i + 3 < UPB) {
            if (tid < KK) my_itm = item[(size_t)(b + 3) * KK + tid];
            if (tid == 0) my_usr = user[b + 3];
        }

        if (i + 1 < UPB) asm volatile("cp.async.wait_group 1;\n" ::: "memory");
        else             asm volatile("cp.async.wait_group 0;\n" ::: "memory");
        __syncthreads();

        // Stage b+3's indices into the freed ring slot and L2-prefetch its
        // rows now: consumed by cp.async at i+2, computed at i+3 -> ~2
        // iterations (~10K cyc) of lead covers straggler DRAM tails.
        if (i + 3 < UPB) {
            if (tid < KK) {
                itm_s[icur][tid] = my_itm;
                const char* p = (const char*)(iw + (size_t)my_itm * HH);
                pf_l2(p);
                pf_l2(p + 128);
            }
            if (tid == 0) usr_s[icur] = my_usr;
        }

        // ---- Compute user b from stage cur: 8 lanes per item ----
        const float ubv = ub_s[cur];
        float4 ua  = ((const float4*)ue_s[cur])[sub];
        float4 ub4 = ((const float4*)ue_s[cur])[sub + 8];
        ua.x += ubv; ua.y += ubv; ua.z += ubv; ua.w += ubv;
        ub4.x += ubv; ub4.y += ubv; ub4.z += ubv; ub4.w += ubv;

        if (warp == 0) {   // ||ue||: lanes 0-7 hold the full vector
            float usq = ua.x*ua.x + ua.y*ua.y + ua.z*ua.z + ua.w*ua.w
                      + ub4.x*ub4.x + ub4.y*ub4.y + ub4.z*ub4.z + ub4.w*ub4.w;
            #pragma unroll
            for (int m = 4; m >= 1; m >>= 1)
                usq += __shfl_xor_sync(0xffffffffu, usq, m);
            if (lane == 0) uacc += sqrtf(usq);
        }

        #pragma unroll
        for (int r = 0; r < 4; ++r) {
            const int k   = r * 16 + slot;
            const bool on = (k < KK);
            const int kc  = on ? k : (KK - 1);  // clamp: keep loads in-bounds

            const float bv = ib_s[cur][kc];
            const float4 wa = ((const float4*)rows_s[cur][kc])[sub];
            const float4 wb = ((const float4*)rows_s[cur][kc])[sub + 8];

            float4 ea, eb;
            ea.x = wa.x + bv; ea.y = wa.y + bv; ea.z = wa.z + bv; ea.w = wa.w + bv;
            eb.x = wb.x + bv; eb.y = wb.y + bv; eb.z = wb.z + bv; eb.w = wb.w + bv;

            float dot = ea.x*ua.x + ea.y*ua.y + ea.z*ua.z + ea.w*ua.w
                      + eb.x*ub4.x + eb.y*ub4.y + eb.z*ub4.z + eb.w*ub4.w;
            float sq  = ea.x*ea.x + ea.y*ea.y + ea.z*ea.z + ea.w*ea.w
                      + eb.x*eb.x + eb.y*eb.y + eb.z*eb.z + eb.w*eb.w;

            #pragma unroll
            for (int m = 4; m >= 1; m >>= 1) {
                dot += __shfl_xor_sync(0xffffffffu, dot, m);
                sq  += __shfl_xor_sync(0xffffffffu, sq,  m);
            }

            if (on && sub == 0) {
                const float pred = dot + gbias;
                pred_s[k] = pred;
                const float d = pred - tgt_s[cur][k];
                macc += d * d;
                nacc += sqrtf(sq);
            }
        }
        __syncthreads();   // pred_s complete; stage cur free; ring slot visible

        // Coalesced prediction store
        if (tid < KK) out[(size_t)b * KK + tid] = pred_s[tid];
    }

    // ---- Block reduce (16 leaders: tid%8==0) + global accumulate ----
    if (sub == 0) { ms_s[slot] = macc; ns_s[slot] = nacc; }
    __syncthreads();
    if (tid == 0) {
        float m = 0.0f, n = 0.0f;
        #pragma unroll
        for (int j = 0; j < 16; ++j) { m += ms_s[j]; n += ns_s[j]; }
        atomicAdd(&g_scratch[0], m);
        atomicAdd(&g_scratch[1], n);
        atomicAdd(&g_scratch[2], uacc);
        __threadfence();
        const unsigned t = atomicAdd(&g_count, 1u);
        if (t == (unsigned)(gridDim.x - 1)) {
            const float s0 = atomicAdd(&g_scratch[0], 0.0f);
            const float s1 = atomicAdd(&g_scratch[1], 0.0f);
            const float s2 = atomicAdd(&g_scratch[2], 0.0f);
            const float inv_bk = 1.0f / (float)((size_t)BB * KK);
            out[(size_t)BB * KK] = s0 * inv_bk
                                 + REGC * (s2 * (1.0f / (float)BB))
                                 + REGC * (s1 * inv_bk);
            g_scratch[0] = 0.0f; g_scratch[1] = 0.0f; g_scratch[2] = 0.0f;
            g_count = 0u;
        }
    }
}

extern "C" void kernel_launch(void* const* d_in, const int* in_sizes, int n_in,
                              void* d_out, int out_size) {
    const float* uw     = (const float*)d_in[0];
    const float* iw     = (const float*)d_in[1];
    const float* ub     = (const float*)d_in[2];
    const float* ib     = (const float*)d_in[3];
    const float* bias   = (const float*)d_in[4];
    const float* target = (const float*)d_in[5];
    const int*   user   = (const int*)d_in[6];
    const int*   item   = (const int*)d_in[7];
    float* out = (float*)d_out;

    mf_pipe_kernel<<<GRID, 128>>>(uw, iw, ub, ib, bias, target, user, item, out);
}

// round 16
// speedup vs baseline: 1.6497x; 1.0058x over previous
#include <cuda_runtime.h>
#include <math.h>

// Problem constants (fixed by the reference)
#define BB   16384
#define KK   50
#define HH   64
#define REGC 0.01f
#define WPB  8          // warps (=users) per block
#define GRID (BB / WPB) // 2048 blocks
#define NR   13         // rounds of 4 rows (last round: 2 rows)
#define PF   3          // load lookahead (rounds in flight)

// [0]=sum sq err, [1]=sum ||ie||, [2]=sum ||ue||
// Statically zero-init; last block re-zeroes after use (invariant per replay).
__device__ float    g_scratch[3];
__device__ unsigned g_count;

__global__ __launch_bounds__(256, 4) void mf_warp_kernel(
    const float* __restrict__ uw,      // [100000,64]
    const float* __restrict__ iw,      // [1000000,64]
    const float* __restrict__ ubp,     // [100000,1]
    const float* __restrict__ ibp,     // [1000000,1]
    const float* __restrict__ bias,    // [1]
    const float* __restrict__ target,  // [B,K]
    const int*   __restrict__ user,    // [B]
    const int*   __restrict__ item,    // [B,K]
    float* __restrict__ out)           // [B*K + 1]
{
    __shared__ float ms_s[WPB], ns_s[WPB], us_s[WPB];

    const int tid  = threadIdx.x;
    const int warp = tid >> 5;
    const int lane = tid & 31;
    const int sub  = lane & 7;     // lane within 8-lane row group
    const int quad = lane >> 3;    // which of 4 rows this group handles/round

    const int b = blockIdx.x * WPB + warp;   // this warp's user

    const float4* __restrict__ iw4 = (const float4*)iw;
    const float4* __restrict__ uw4 = (const float4*)uw;

    // ---- User embedding into registers (8 floats/lane; quads replicated) ----
    const int   u   = user[b];
    const float ubv = ubp[u];
    float4 ua  = uw4[(size_t)u * 16 + sub];
    float4 ub4 = uw4[(size_t)u * 16 + 8 + sub];
    ua.x += ubv; ua.y += ubv; ua.z += ubv; ua.w += ubv;
    ub4.x += ubv; ub4.y += ubv; ub4.z += ubv; ub4.w += ubv;

    float usq = ua.x*ua.x + ua.y*ua.y + ua.z*ua.z + ua.w*ua.w
              + ub4.x*ub4.x + ub4.y*ub4.y + ub4.z*ub4.z + ub4.w*ub4.w;
    #pragma unroll
    for (int m = 4; m >= 1; m >>= 1)
        usq += __shfl_xor_sync(0xffffffffu, usq, m);
    const float unorm = sqrtf(usq);      // full ||ue|| in every lane

    const float gbias = bias[0];

    // ---- All 50 item indices into distributed registers (lane l < 25 holds
    //      rows 2l, 2l+1) ----
    int2 myi = make_int2(0, 0);
    if (lane < 25) myi = ((const int2*)(item + (size_t)b * KK))[lane];

    // ---- Register ring: up to PF rounds of loads in flight ----
    float4 wa[PF], wb[PF];
    float  ibv[PF], tg[PF];
    int    rowq[PF];                     // this lane's row in round s (or -1)

    // ISSUE(s): gather round s's 4 rows (one per quad) into ring slot s%PF
    #define ISSUE(s)                                                          \
    {                                                                         \
        const int row = 4 * (s) + quad;                                       \
        const bool act = (row < KK);                                          \
        const int p  = row >> 1;                                              \
        const int ia = __shfl_sync(0xffffffffu, myi.x, p < 25 ? p : 0);       \
        const int ic = __shfl_sync(0xffffffffu, myi.y, p < 25 ? p : 0);       \
        int idx = (row & 1) ? ic : ia;                                        \
        if (!act) idx = 0;                                                    \
        const float4* base = iw4 + (size_t)idx * 16;                          \
        wa[(s) % PF]  = base[sub];                                            \
        wb[(s) % PF]  = base[8 + sub];                                        \
        ibv[(s) % PF] = ibp[idx];                                             \
        tg[(s) % PF]  = (sub == 0 && act)                                     \
                          ? target[(size_t)b * KK + row] : 0.0f;              \
        rowq[(s) % PF] = act ? row : -1;                                      \
    }

    #pragma unroll
    for (int s = 0; s < PF; ++s) ISSUE(s);

    float macc = 0.0f, nacc = 0.0f;

    #pragma unroll
    for (int r = 0; r < NR; ++r) {
        const int j = r % PF;

        // Consume slot j into locals BEFORE re-issuing into it (R15 bug fix:
        // ISSUE(r+PF) targets this same slot).
        const float4 lwa = wa[j];
        const float4 lwb = wb[j];
        const float  lbv = ibv[j];
        const float  ltg = tg[j];
        const int    lrw = rowq[j];

        if (r + PF < NR) ISSUE(r + PF);

        float4 ea, eb;
        ea.x = lwa.x + lbv; ea.y = lwa.y + lbv;
        ea.z = lwa.z + lbv; ea.w = lwa.w + lbv;
        eb.x = lwb.x + lbv; eb.y = lwb.y + lbv;
        eb.z = lwb.z + lbv; eb.w = lwb.w + lbv;

        float dot = ea.x*ua.x + ea.y*ua.y + ea.z*ua.z + ea.w*ua.w
                  + eb.x*ub4.x + eb.y*ub4.y + eb.z*ub4.z + eb.w*ub4.w;
        float sq  = ea.x*ea.x + ea.y*ea.y + ea.z*ea.z + ea.w*ea.w
                  + eb.x*eb.x + eb.y*eb.y + eb.z*eb.z + eb.w*eb.w;

        // 3-level butterfly within the 8-lane group (4 rows share each SHFL)
        #pragma unroll
        for (int m = 4; m >= 1; m >>= 1) {
            dot += __shfl_xor_sync(0xffffffffu, dot, m);
            sq  += __shfl_xor_sync(0xffffffffu, sq,  m);
        }

        if (sub == 0 && lrw >= 0) {
            const float pred = dot + gbias;
            out[(size_t)b * KK + lrw] = pred;
            const float d = pred - ltg;
            macc += d * d;
            nacc += sqrtf(sq);
        }
    }
    #undef ISSUE

    // ---- Fold the 4 quad-leaders (lanes 0,8,16,24; others carry 0) ----
    macc += __shfl_xor_sync(0xffffffffu, macc, 8);
    macc += __shfl_xor_sync(0xffffffffu, macc, 16);
    nacc += __shfl_xor_sync(0xffffffffu, nacc, 8);
    nacc += __shfl_xor_sync(0xffffffffu, nacc, 16);

    if (lane == 0) { ms_s[warp] = macc; ns_s[warp] = nacc; us_s[warp] = unorm; }
    __syncthreads();

    if (tid == 0) {
        float m = 0.0f, n = 0.0f, uu = 0.0f;
        #pragma unroll
        for (int j = 0; j < WPB; ++j) { m += ms_s[j]; n += ns_s[j]; uu += us_s[j]; }
        atomicAdd(&g_scratch[0], m);
        atomicAdd(&g_scratch[1], n);
        atomicAdd(&g_scratch[2], uu);
        __threadfence();
        const unsigned t = atomicAdd(&g_count, 1u);
        if (t == (unsigned)(gridDim.x - 1)) {
            const float s0 = atomicAdd(&g_scratch[0], 0.0f);
            const float s1 = atomicAdd(&g_scratch[1], 0.0f);
            const float s2 = atomicAdd(&g_scratch[2], 0.0f);
            const float inv_bk = 1.0f / (float)((size_t)BB * KK);
            out[(size_t)BB * KK] = s0 * inv_bk
                                 + REGC * (s2 * (1.0f / (float)BB))
                                 + REGC * (s1 * inv_bk);
            g_scratch[0] = 0.0f; g_scratch[1] = 0.0f; g_scratch[2] = 0.0f;
            g_count = 0u;
        }
    }
}

extern "C" void kernel_launch(void* const* d_in, const int* in_sizes, int n_in,
                              void* d_out, int out_size) {
    const float* uw     = (const float*)d_in[0];
    const float* iw     = (const float*)d_in[1];
    const float* ubp    = (const float*)d_in[2];
    const float* ibp    = (const float*)d_in[3];
    const float* bias   = (const float*)d_in[4];
    const float* target = (const float*)d_in[5];
    const int*   user   = (const int*)d_in[6];
    const int*   item   = (const int*)d_in[7];
    float* out = (float*)d_out;

    mf_warp_kernel<<<GRID, 32 * WPB>>>(uw, iw, ubp, ibp, bias, target, user, item, out);
}